// round 14
// baseline (speedup 1.0000x reference)
#include <cuda_runtime.h>
#include <cuda_fp16.h>
#include <math.h>
#include <stdint.h>

// Problem constants
#define B_  8
#define C_  128
#define H_  64
#define W_  64
#define O_  128
#define K2_ 9
#define E_  1152   // C_*K2_
#define NPIX (B_*H_*W_)      // 32768
#define PITCH 576            // u32 per pixel row of cols (1152 fp16 / 2)

// Scratch (device globals; no allocation allowed)
__device__ float    g_xT [B_*H_*W_*C_];      // NHWC fp32 (for bilinear sampling)
__device__ uint32_t g_xh [B_*H_*W_*C_/2];    // NHWC fp16x2
__device__ float    g_offmask[NPIX*27];      // 18 offsets + 9 sigmoided masks / pixel
__device__ uint32_t g_wh [K2_*O_*C_/2];      // main weight fp16x2, [k2][oc][c/2]
__device__ uint32_t g_owh[10*32*C_/2];       // offset/mask weight fp16x2 (k2=9 zeros)
__device__ uint32_t g_colh[NPIX*PITCH];      // sampled cols fp16x2, [pix][k2][c/2]

// ===========================================================================
// Helpers (baseline PTX: ldmatrix + mma.sync + cp.async)
// ===========================================================================
__device__ __forceinline__ uint32_t smem_u32(const void* p) {
    uint32_t a;
    asm("{ .reg .u64 t; cvta.to.shared.u64 t, %1; cvt.u32.u64 %0, t; }"
        : "=r"(a) : "l"(p));
    return a;
}
__device__ __forceinline__ void ldsm4(uint32_t* r, uint32_t addr) {
    asm volatile("ldmatrix.sync.aligned.m8n8.x4.shared.b16 {%0,%1,%2,%3}, [%4];"
        : "=r"(r[0]), "=r"(r[1]), "=r"(r[2]), "=r"(r[3]) : "r"(addr));
}
__device__ __forceinline__ void ldsm2(uint32_t* r, uint32_t addr) {
    asm volatile("ldmatrix.sync.aligned.m8n8.x2.shared.b16 {%0,%1}, [%2];"
        : "=r"(r[0]), "=r"(r[1]) : "r"(addr));
}
__device__ __forceinline__ void mma16816(float* c, const uint32_t* a, const uint32_t* b) {
    asm volatile(
        "mma.sync.aligned.m16n8k16.row.col.f32.f16.f16.f32 "
        "{%0,%1,%2,%3}, {%4,%5,%6,%7}, {%8,%9}, {%0,%1,%2,%3};"
        : "+f"(c[0]), "+f"(c[1]), "+f"(c[2]), "+f"(c[3])
        : "r"(a[0]), "r"(a[1]), "r"(a[2]), "r"(a[3]), "r"(b[0]), "r"(b[1]));
}
#define CP_A16(dst, src) \
    asm volatile("cp.async.cg.shared.global [%0], [%1], 16;" \
                 :: "r"(dst), "l"(src))
#define CP_A16Z(dst, src, sz) \
    asm volatile("cp.async.cg.shared.global [%0], [%1], 16, %2;" \
                 :: "r"(dst), "l"(src), "r"(sz))
#define CP_COMMIT() asm volatile("cp.async.commit_group;")
#define CP_WAIT(n)  asm volatile("cp.async.wait_group %0;" :: "n"(n))

__device__ __forceinline__ uint32_t f16pack(float a, float b) {
    __half2 h = __floats2half2_rn(a, b);
    return *(uint32_t*)&h;
}

// ===========================================================================
// Kernel A: NCHW -> NHWC transpose + fp16 convert (smem tile, coalesced)
// ===========================================================================
__global__ void __launch_bounds__(256) transpose_kernel(const float* __restrict__ x) {
    __shared__ float ts[32][65];
    int bi  = blockIdx.x;
    int ct  = bi & 3;
    int rem = bi >> 2;
    int y   = rem & 63;
    int b   = rem >> 6;
    int c0  = ct * 32;
    int t   = threadIdx.x;

    #pragma unroll
    for (int it = 0; it < 8; it++) {
        int idx = it*256 + t;
        int cl = idx >> 6, xw = idx & 63;
        ts[cl][xw] = x[((b*C_ + c0 + cl)*H_ + y)*W_ + xw];
    }
    __syncthreads();
    #pragma unroll
    for (int it = 0; it < 8; it++) {
        int idx = it*256 + t;
        int cl = idx & 31, xw = idx >> 5;
        g_xT[((b*H_ + y)*W_ + xw)*C_ + c0 + cl] = ts[cl][xw];
    }
    #pragma unroll
    for (int it = 0; it < 4; it++) {
        int idx = it*256 + t;
        int cp = idx & 15, xw = idx >> 4;
        int o = ((b*H_ + y)*W_ + xw)*64 + (c0 >> 1) + cp;
        g_xh[o] = f16pack(ts[cp*2][xw], ts[cp*2 + 1][xw]);
    }
}

// ===========================================================================
// Kernel A2: main weight fp16 pack into [k2][oc][c] fp16x2
// ===========================================================================
__global__ void wsplit_kernel(const float* __restrict__ w) {
    int i2 = blockIdx.x * blockDim.x + threadIdx.x;
    if (i2 >= K2_*O_*C_/2) return;
    int cpair = i2 & 63;
    int oc    = (i2 >> 6) & 127;
    int k2    = i2 >> 13;
    int c = cpair * 2;
    g_wh[i2] = f16pack(w[oc*E_ + c*K2_ + k2], w[oc*E_ + (c+1)*K2_ + k2]);
}

// ===========================================================================
// Kernel A3: offset/mask weight pack (10 k2 chunks; k2=9 all-zero pad)
// ===========================================================================
__global__ void owpack_kernel(const float* __restrict__ offw,
                              const float* __restrict__ maskw) {
    int i2 = blockIdx.x * blockDim.x + threadIdx.x;
    if (i2 >= 10*32*C_/2) return;
    int cp  = i2 & 63;
    int oc  = (i2 >> 6) & 31;
    int k2  = i2 >> 11;
    int c = cp * 2;
    float v0 = 0.f, v1 = 0.f;
    if (k2 < 9) {
        if (oc < 18) {
            v0 = offw[oc*E_ + c*K2_ + k2];
            v1 = offw[oc*E_ + (c+1)*K2_ + k2];
        } else if (oc < 27) {
            v0 = maskw[(oc-18)*E_ + c*K2_ + k2];
            v1 = maskw[(oc-18)*E_ + (c+1)*K2_ + k2];
        }
    }
    g_owh[i2] = f16pack(v0, v1);
}

// ===========================================================================
// Kernel B: offset+mask conv via HMMA fp16, K=256 per stage (k2 pairs,
// k2=9 zero-padded). Block = 64 pix x 32 oc, 256 thr, 2 blk/SM. Grid 512.
// Row stride 528 B (== 16 mod 128 -> conflict-free ldmatrix).
// ===========================================================================
#define OM_STRIDE 528
#define OM_A 0
#define OM_B 33792                    // 64*528
#define OM_SLOT 50688                 // + 32*528
#define OM_BIAS (2*OM_SLOT)           // 101376
#define OM_TOTAL (2*OM_SLOT + 128)    // 101504

__global__ void __launch_bounds__(256, 2) offmask_mma_kernel(
    const float* __restrict__ offb, const float* __restrict__ maskb) {
    extern __shared__ char smem[];
    uint32_t sb = smem_u32(smem);
    const int t    = threadIdx.x;
    const int lane = t & 31;
    const int wid  = t >> 5;        // 0..7
    const int bi   = blockIdx.x;    // 512
    const int b    = bi >> 6;
    const int row  = bi & 63;

    float* bias_s = (float*)(smem + OM_BIAS);
    if (t < 32)
        bias_s[t] = (t < 18) ? offb[t] : (t < 27 ? maskb[t-18] : 0.f);

    const int warp_m = wid >> 1;    // 4 groups of 16 pixels
    const int warp_n = wid & 1;     // 2 groups of 16 oc
    const uint32_t aOff = (uint32_t)((warp_m*16 + (lane & 15))*OM_STRIDE + (lane >> 4)*16);
    const uint32_t bOff = (uint32_t)((warp_n*16 + (lane & 7))*OM_STRIDE + ((lane >> 3) & 1)*16);

    float acc[2][4];
    #pragma unroll
    for (int i = 0; i < 2; i++)
        #pragma unroll
        for (int j = 0; j < 4; j++) acc[i][j] = 0.f;

    // A staging: 4 threads per pixel
    const int m   = t >> 2;         // pixel (col) 0..63
    const int q   = t & 3;          // quarter
    const int col = m;

    // stage k2 pair (2*kp, 2*kp+1) into slot kp&1
    auto stage = [&](int kp) {
        uint32_t slot = (uint32_t)((kp & 1) * OM_SLOT);
        // B chunk: 32 oc x 2 k2 x 16 chunks = 1024 / 256 thr = 4 each
        #pragma unroll
        for (int it = 0; it < 4; it++) {
            int idx = it*256 + t;
            int oc   = idx >> 5;
            int gh   = idx & 31;
            int half = gh >> 4;
            int g    = gh & 15;
            int k2   = kp*2 + half;
            uint32_t so = slot + (uint32_t)(oc*OM_STRIDE + half*256 + g*16);
            CP_A16(sb + OM_B + so, &g_owh[k2*2048 + oc*64 + g*4]);
        }
        // A chunk: im2col for both k2 halves, zero-fill out-of-range
        #pragma unroll
        for (int half = 0; half < 2; half++) {
            int k2 = kp*2 + half;
            int ki = k2 / 3, kj = k2 - ki*3;
            int sy = row - 1 + ki;
            int sx = col - 1 + kj;
            bool valid = (k2 < 9) && (sy >= 0) && (sy < H_) && (sx >= 0) && (sx < W_);
            uint32_t sz = valid ? 16u : 0u;
            int syc = valid ? sy : 0;
            int sxc = valid ? sx : 0;
            int gb = ((b*H_ + syc)*W_ + sxc)*64 + q*16;
            uint32_t abase = slot + (uint32_t)(m*OM_STRIDE + half*256 + q*64);
            #pragma unroll
            for (int j4 = 0; j4 < 4; j4++)
                CP_A16Z(sb + OM_A + abase + j4*16, &g_xh[gb + j4*4], sz);
        }
        CP_COMMIT();
    };

    stage(0);
    for (int kp = 0; kp < 5; kp++) {
        if (kp < 4) { stage(kp+1); CP_WAIT(1); }
        else        { CP_WAIT(0); }
        __syncthreads();

        uint32_t slot = (uint32_t)((kp & 1) * OM_SLOT);

        // ---- software-pipelined MMA: 16 ksteps ----
        uint32_t afr[2][4];
        uint32_t bfr[2][2][2];
        auto ldf = [&](int ks, int buf) {
            uint32_t ab = sb + slot + OM_A + aOff + ks*32;
            uint32_t bb = sb + slot + OM_B + bOff + ks*32;
            ldsm4(afr[buf], ab);
            ldsm2(bfr[buf][0], bb);
            ldsm2(bfr[buf][1], bb + 8*OM_STRIDE);
        };
        ldf(0, 0);
        #pragma unroll
        for (int s = 0; s < 16; s++) {
            if (s < 15) ldf(s+1, (s+1)&1);
            int bu = s & 1;
            mma16816(acc[0], afr[bu], bfr[bu][0]);
            mma16816(acc[1], afr[bu], bfr[bu][1]);
        }
        __syncthreads();
    }

    // epilogue: bias + sigmoid, scatter
    const int r0  = lane >> 2;
    const int cl0 = (lane & 3)*2;
    #pragma unroll
    for (int nt = 0; nt < 2; nt++) {
        #pragma unroll
        for (int j = 0; j < 4; j++) {
            int oc = warp_n*16 + nt*8 + cl0 + (j & 1);
            if (oc >= 27) continue;
            int pcol = warp_m*16 + r0 + (j >> 1)*8;
            int gpix = (b*H_ + row)*W_ + pcol;
            float v = acc[nt][j] + bias_s[oc];
            if (oc >= 18) v = 1.f / (1.f + expf(-v));
            g_offmask[gpix*27 + oc] = v;
        }
    }
}

// ===========================================================================
// Kernel S: sample cols to gmem (fp16). One warp per (pixel, k2) task.
// ===========================================================================
__global__ void __launch_bounds__(256) sample_cols_kernel() {
    int task = blockIdx.x * 8 + (threadIdx.x >> 5);
    int lane = threadIdx.x & 31;
    int pix = task / 9;
    int k2  = task - pix*9;
    int b   = pix >> 12;
    int rem = pix & 4095;
    int row = rem >> 6;
    int col = rem & 63;

    float offy = g_offmask[pix*27 + 2*k2];
    float offx = g_offmask[pix*27 + 2*k2 + 1];
    float msk  = g_offmask[pix*27 + 18 + k2];
    int ki = k2 / 3, kj = k2 - ki*3;
    float py = (float)(row - 1 + ki) + offy;
    float px = (float)(col - 1 + kj) + offx;
    float y0f = floorf(py), x0f = floorf(px);
    float ly = py - y0f, lx = px - x0f;
    int y0 = (int)y0f, x0 = (int)x0f;
    float w00 = (1.f-ly)*(1.f-lx)*msk;
    float w01 = (1.f-ly)*lx*msk;
    float w10 = ly*(1.f-lx)*msk;
    float w11 = ly*lx*msk;
    bool vy0 = (y0 >= 0) && (y0 < H_);
    bool vy1 = (y0+1 >= 0) && (y0+1 < H_);
    bool vx0 = (x0 >= 0) && (x0 < W_);
    bool vx1 = (x0+1 >= 0) && (x0+1 < W_);
    bool p00 = vy0 && vx0, p01 = vy0 && vx1;
    bool p10 = vy1 && vx0, p11 = vy1 && vx1;
    const float4* xb4 = (const float4*)g_xT + (size_t)b * H_ * W_ * 32;
    int i00 = (y0*W_ + x0)*32 + lane;
    float4 zero = make_float4(0.f, 0.f, 0.f, 0.f);
    float4 v00 = p00 ? xb4[i00           ] : zero;
    float4 v01 = p01 ? xb4[i00 + 32      ] : zero;
    float4 v10 = p10 ? xb4[i00 + W_*32   ] : zero;
    float4 v11 = p11 ? xb4[i00 + W_*32+32] : zero;
    float r0 = w00*v00.x + w01*v01.x + w10*v10.x + w11*v11.x;
    float r1 = w00*v00.y + w01*v01.y + w10*v10.y + w11*v11.y;
    float r2 = w00*v00.z + w01*v01.z + w10*v10.z + w11*v11.z;
    float r3 = w00*v00.w + w01*v01.w + w10*v10.w + w11*v11.w;
    int o = pix*PITCH + k2*64 + lane*2;
    *(uint2*)&g_colh[o] = make_uint2(f16pack(r0, r1), f16pack(r2, r3));
}

// ===========================================================================
// Kernel C: pure GEMM fp16, K=128 per stage (one k2 per iteration, 9 iters).
// Block = 64 pix (1 row) x 128 oc, 256 threads, 2 blocks/SM. Grid 512.
// Warp tile 32 pix x 32 oc (warp grid 2x4). Row stride 272 B.
// ===========================================================================
#define G_STRIDE 272
#define G_A 0
#define G_W 17408                    // 64*272
#define G_SLOT 52224                 // + 128*272
#define G_TOTAL (2*G_SLOT)           // 104448

__global__ void __launch_bounds__(256, 2) dcn_gemm_kernel(float* __restrict__ out) {
    extern __shared__ char smem[];
    uint32_t sb = smem_u32(smem);
    const int t    = threadIdx.x;
    const int lane = t & 31;
    const int wid  = t >> 5;        // 0..7
    const int bi   = blockIdx.x;    // 512 blocks, pixels [bi*64, bi*64+64)
    const int b    = bi >> 6;
    const int row  = bi & 63;

    const int warp_m = wid & 1;     // 2 groups of 32 pixels
    const int warp_n = wid >> 1;    // 4 groups of 32 oc
    const uint32_t a_off = (uint32_t)((warp_m*32 + (lane & 15))*G_STRIDE + (lane >> 4)*16);
    const uint32_t b_off = (uint32_t)((warp_n*32 + (lane & 7))*G_STRIDE + ((lane >> 3) & 1)*16);

    float acc[2][4][4];
    #pragma unroll
    for (int i = 0; i < 2; i++)
        #pragma unroll
        for (int j = 0; j < 4; j++)
            #pragma unroll
            for (int k = 0; k < 4; k++) acc[i][j][k] = 0.f;

    // A staging: 4 threads per pixel (quarters of the 64-u32 k2 row)
    const int sp = t >> 2;          // pixel 0..63
    const int sq = t & 3;
    const int gA = (bi*64 + sp) * PITCH;

    auto stage = [&](int k2) {
        uint32_t slot = (uint32_t)((k2 & 1) * G_SLOT);
        // A: 64 pix x 256B; 4 x 16B per thread
        uint32_t aso = slot + (uint32_t)(sp*G_STRIDE + sq*64);
        int gsrc = gA + k2*64 + sq*16;
        #pragma unroll
        for (int j = 0; j < 4; j++)
            CP_A16(sb + G_A + aso + j*16, &g_colh[gsrc + j*4]);
        // W: 128 oc x 256B = 2048 x 16B; 8 per thread
        #pragma unroll
        for (int it = 0; it < 8; it++) {
            int idx = it*256 + t;           // 0..2047
            int oc = idx >> 4;
            int g  = idx & 15;
            uint32_t so = slot + (uint32_t)(oc*G_STRIDE + g*16);
            CP_A16(sb + G_W + so, &g_wh[k2*8192 + oc*64 + g*4]);
        }
        CP_COMMIT();
    };

    stage(0);
    for (int k2 = 0; k2 < K2_; k2++) {
        if (k2 < K2_-1) { stage(k2+1); CP_WAIT(1); }
        else            { CP_WAIT(0); }
        __syncthreads();

        uint32_t slot = (uint32_t)((k2 & 1) * G_SLOT);

        // ---- software-pipelined MMA: 8 ksteps ----
        uint32_t afr[2][2][4];
        uint32_t bfr[2][4][2];
        auto ldf = [&](int ks, int buf) {
            uint32_t ab = sb + slot + G_A + a_off + ks*32;
            uint32_t bb = sb + slot + G_W + b_off + ks*32;
            ldsm4(afr[buf][0], ab);
            ldsm4(afr[buf][1], ab + 16*G_STRIDE);
            ldsm2(bfr[buf][0], bb);
            ldsm2(bfr[buf][1], bb + 8*G_STRIDE);
            ldsm2(bfr[buf][2], bb + 16*G_STRIDE);
            ldsm2(bfr[buf][3], bb + 24*G_STRIDE);
        };
        ldf(0, 0);
        #pragma unroll
        for (int s = 0; s < 8; s++) {
            if (s < 7) ldf(s+1, (s+1)&1);
            int bu = s & 1;
            #pragma unroll
            for (int mt = 0; mt < 2; mt++)
                #pragma unroll
                for (int nt = 0; nt < 4; nt++)
                    mma16816(acc[mt][nt], afr[bu][mt], bfr[bu][nt]);
        }
        __syncthreads();
    }

    // ---- epilogue: transpose through smem, coalesced NCHW stores ----
    float* O_s = (float*)smem;     // [oc][pix 64], stride 68 (34816 B < smem)
    const int g   = lane >> 2;
    const int tig = lane & 3;
    #pragma unroll
    for (int mt = 0; mt < 2; mt++) {
        #pragma unroll
        for (int nt = 0; nt < 4; nt++) {
            int p0 = warp_m*32 + mt*16 + g;
            int o0 = warp_n*32 + nt*8 + tig*2;
            O_s[(o0  )*68 + p0    ] = acc[mt][nt][0];
            O_s[(o0+1)*68 + p0    ] = acc[mt][nt][1];
            O_s[(o0  )*68 + p0 + 8] = acc[mt][nt][2];
            O_s[(o0+1)*68 + p0 + 8] = acc[mt][nt][3];
        }
    }
    __syncthreads();
    // 128 oc x 64 pix = 8192 / 256 = 32 iterations
    #pragma unroll 4
    for (int it = 0; it < 32; it++) {
        int idx = it*256 + t;
        int oc = idx >> 6;
        int p  = idx & 63;
        out[(((size_t)b*O_ + oc)*H_ + row)*W_ + p] = O_s[oc*68 + p];
    }
}

// ===========================================================================
extern "C" void kernel_launch(void* const* d_in, const int* in_sizes, int n_in,
                              void* d_out, int out_size) {
    const float* x      = (const float*)d_in[0];
    const float* weight = (const float*)d_in[1];
    const float* offw   = (const float*)d_in[2];
    const float* offb   = (const float*)d_in[3];
    const float* maskw  = (const float*)d_in[4];
    const float* maskb  = (const float*)d_in[5];
    float* out = (float*)d_out;

    static bool attr_set = false;
    if (!attr_set) {
        cudaFuncSetAttribute(offmask_mma_kernel,
            cudaFuncAttributeMaxDynamicSharedMemorySize, OM_TOTAL);
        cudaFuncSetAttribute(dcn_gemm_kernel,
            cudaFuncAttributeMaxDynamicSharedMemorySize, G_TOTAL);
        attr_set = true;
    }

    transpose_kernel<<<B_*H_*4, 256>>>(x);
    wsplit_kernel<<<(K2_*O_*C_/2 + 255)/256, 256>>>(weight);
    owpack_kernel<<<(10*32*C_/2 + 255)/256, 256>>>(offw, maskw);
    offmask_mma_kernel<<<512, 256, OM_TOTAL>>>(offb, maskb);
    sample_cols_kernel<<<NPIX*K2_/8, 256>>>();
    dcn_gemm_kernel<<<512, 256, G_TOTAL>>>(out);
}

// round 15
// speedup vs baseline: 1.0729x; 1.0729x over previous
#include <cuda_runtime.h>
#include <cuda_fp16.h>
#include <math.h>
#include <stdint.h>

// Problem constants
#define B_  8
#define C_  128
#define H_  64
#define W_  64
#define O_  128
#define K2_ 9
#define E_  1152   // C_*K2_
#define NPIX (B_*H_*W_)      // 32768
#define PITCH 576            // u32 per pixel row of cols (1152 fp16 / 2)

// Scratch (device globals; no allocation allowed)
__device__ uint32_t g_xh [B_*H_*W_*C_/2];    // NHWC fp16x2
__device__ float    g_offmask[NPIX*27];      // 18 offsets + 9 sigmoided masks / pixel
__device__ uint32_t g_wh [K2_*O_*C_/2];      // main weight fp16x2, [k2][oc][c/2]
__device__ uint32_t g_owh[K2_*32*C_/2];      // offset/mask weight fp16x2
__device__ uint32_t g_colh[NPIX*PITCH];      // sampled cols fp16x2, [pix][k2][c/2]

// ===========================================================================
// Helpers (baseline PTX: ldmatrix + mma.sync + cp.async)
// ===========================================================================
__device__ __forceinline__ uint32_t smem_u32(const void* p) {
    uint32_t a;
    asm("{ .reg .u64 t; cvta.to.shared.u64 t, %1; cvt.u32.u64 %0, t; }"
        : "=r"(a) : "l"(p));
    return a;
}
__device__ __forceinline__ void ldsm4(uint32_t* r, uint32_t addr) {
    asm volatile("ldmatrix.sync.aligned.m8n8.x4.shared.b16 {%0,%1,%2,%3}, [%4];"
        : "=r"(r[0]), "=r"(r[1]), "=r"(r[2]), "=r"(r[3]) : "r"(addr));
}
__device__ __forceinline__ void ldsm2(uint32_t* r, uint32_t addr) {
    asm volatile("ldmatrix.sync.aligned.m8n8.x2.shared.b16 {%0,%1}, [%2];"
        : "=r"(r[0]), "=r"(r[1]) : "r"(addr));
}
__device__ __forceinline__ void mma16816(float* c, const uint32_t* a, const uint32_t* b) {
    asm volatile(
        "mma.sync.aligned.m16n8k16.row.col.f32.f16.f16.f32 "
        "{%0,%1,%2,%3}, {%4,%5,%6,%7}, {%8,%9}, {%0,%1,%2,%3};"
        : "+f"(c[0]), "+f"(c[1]), "+f"(c[2]), "+f"(c[3])
        : "r"(a[0]), "r"(a[1]), "r"(a[2]), "r"(a[3]), "r"(b[0]), "r"(b[1]));
}
#define CP_A16(dst, src) \
    asm volatile("cp.async.cg.shared.global [%0], [%1], 16;" \
                 :: "r"(dst), "l"(src))
#define CP_A16Z(dst, src, sz) \
    asm volatile("cp.async.cg.shared.global [%0], [%1], 16, %2;" \
                 :: "r"(dst), "l"(src), "r"(sz))
#define CP_COMMIT() asm volatile("cp.async.commit_group;")
#define CP_WAIT(n)  asm volatile("cp.async.wait_group %0;" :: "n"(n))

__device__ __forceinline__ uint32_t f16pack(float a, float b) {
    __half2 h = __floats2half2_rn(a, b);
    return *(uint32_t*)&h;
}

// ===========================================================================
// Kernel A: NCHW -> NHWC transpose -> fp16x2 (smem tile, coalesced)
// ===========================================================================
__global__ void __launch_bounds__(256) transpose_kernel(const float* __restrict__ x) {
    __shared__ float ts[32][65];
    int bi  = blockIdx.x;
    int ct  = bi & 3;
    int rem = bi >> 2;
    int y   = rem & 63;
    int b   = rem >> 6;
    int c0  = ct * 32;
    int t   = threadIdx.x;

    #pragma unroll
    for (int it = 0; it < 8; it++) {
        int idx = it*256 + t;
        int cl = idx >> 6, xw = idx & 63;
        ts[cl][xw] = x[((b*C_ + c0 + cl)*H_ + y)*W_ + xw];
    }
    __syncthreads();
    #pragma unroll
    for (int it = 0; it < 4; it++) {
        int idx = it*256 + t;
        int cp = idx & 15, xw = idx >> 4;
        int o = ((b*H_ + y)*W_ + xw)*64 + (c0 >> 1) + cp;
        g_xh[o] = f16pack(ts[cp*2][xw], ts[cp*2 + 1][xw]);
    }
}

// ===========================================================================
// Kernel A2: main weight fp16 pack into [k2][oc][c] fp16x2
// ===========================================================================
__global__ void wsplit_kernel(const float* __restrict__ w) {
    int i2 = blockIdx.x * blockDim.x + threadIdx.x;
    if (i2 >= K2_*O_*C_/2) return;
    int cpair = i2 & 63;
    int oc    = (i2 >> 6) & 127;
    int k2    = i2 >> 13;
    int c = cpair * 2;
    g_wh[i2] = f16pack(w[oc*E_ + c*K2_ + k2], w[oc*E_ + (c+1)*K2_ + k2]);
}

// ===========================================================================
// Kernel A3: offset/mask weight pack (oc 0..17 offw, 18..26 maskw, rest 0)
// ===========================================================================
__global__ void owpack_kernel(const float* __restrict__ offw,
                              const float* __restrict__ maskw) {
    int i2 = blockIdx.x * blockDim.x + threadIdx.x;
    if (i2 >= K2_*32*C_/2) return;
    int cp  = i2 & 63;
    int oc  = (i2 >> 6) & 31;
    int k2  = i2 >> 11;
    int c = cp * 2;
    float v0 = 0.f, v1 = 0.f;
    if (oc < 18) {
        v0 = offw[oc*E_ + c*K2_ + k2];
        v1 = offw[oc*E_ + (c+1)*K2_ + k2];
    } else if (oc < 27) {
        v0 = maskw[(oc-18)*E_ + c*K2_ + k2];
        v1 = maskw[(oc-18)*E_ + (c+1)*K2_ + k2];
    }
    g_owh[i2] = f16pack(v0, v1);
}

// ===========================================================================
// Kernel B: offset+mask conv via HMMA fp16, 4-slot cp.async ring.
// Block = 64 pix (1 row) x 32 oc, 256 threads, 2 blocks/SM. Grid 512.
// Warp tile 16 pix x 16 oc. A row stride 272 B.
// ===========================================================================
#define OM_SLOT 26112
#define OM_A 0
#define OM_B 17408
#define OM_DEPTH 4
#define OM_BIAS (OM_DEPTH*OM_SLOT)          // 104448
#define OM_TOTAL (OM_DEPTH*OM_SLOT + 128)   // 104576

__global__ void __launch_bounds__(256, 2) offmask_mma_kernel(
    const float* __restrict__ offb, const float* __restrict__ maskb) {
    extern __shared__ char smem[];
    uint32_t sb = smem_u32(smem);
    const int t    = threadIdx.x;
    const int lane = t & 31;
    const int wid  = t >> 5;        // 0..7
    const int bi   = blockIdx.x;    // 512
    const int b    = bi >> 6;
    const int row  = bi & 63;

    float* bias_s = (float*)(smem + OM_BIAS);
    if (t < 32)
        bias_s[t] = (t < 18) ? offb[t] : (t < 27 ? maskb[t-18] : 0.f);

    const int warp_m = wid >> 1;    // 4 groups of 16 pixels
    const int warp_n = wid & 1;     // 2 groups of 16 oc
    const uint32_t aOff = (uint32_t)((warp_m*16 + (lane & 15))*272 + (lane >> 4)*16);
    const uint32_t bOff = (uint32_t)((warp_n*16 + (lane & 7))*272 + ((lane >> 3) & 1)*16);

    float acc[2][4];
    #pragma unroll
    for (int i = 0; i < 2; i++)
        #pragma unroll
        for (int j = 0; j < 4; j++) acc[i][j] = 0.f;

    // A staging: 4 threads per pixel (quarters of the 64-u32 row)
    const int m   = t >> 2;         // pixel (col) 0..63
    const int q   = t & 3;          // quarter
    const int col = m;

    auto stage = [&](int k2, uint32_t slot) {
        // B chunk: 2048 u32 / 256 threads = 2 x 16B each
        #pragma unroll
        for (int it = 0; it < 2; it++) {
            int idx = it*256 + t;
            int oc = idx >> 4;
            int g  = idx & 15;
            int gi = k2*2048 + oc*64 + g*4;
            uint32_t so = slot + (uint32_t)(oc*272 + g*16);
            CP_A16(sb + OM_B + so, &g_owh[gi]);
        }
        // A chunk: im2col with zero-fill
        int ki = k2 / 3, kj = k2 - ki*3;
        int sy = row - 1 + ki;
        int sx = col - 1 + kj;
        bool valid = (sy >= 0) && (sy < H_) && (sx >= 0) && (sx < W_);
        uint32_t sz = valid ? 16u : 0u;
        int syc = valid ? sy : 0;
        int sxc = valid ? sx : 0;
        int gb = ((b*H_ + syc)*W_ + sxc)*64 + q*16;
        uint32_t abase = slot + (uint32_t)(m*272 + q*64);
        #pragma unroll
        for (int j4 = 0; j4 < 4; j4++)
            CP_A16Z(sb + OM_A + abase + j4*16, &g_xh[gb + j4*4], sz);
        CP_COMMIT();
    };

    stage(0, 0);
    stage(1, OM_SLOT);
    stage(2, 2*OM_SLOT);
    stage(3, 3*OM_SLOT);
    uint32_t cons = 0;
    for (int k2 = 0; k2 < K2_; k2++) {
        CP_WAIT(3);            // group k2 complete
        __syncthreads();

        // ---- software-pipelined MMA: 8 ksteps ----
        uint32_t afr[2][4];
        uint32_t bfr[2][2][2];
        auto ldf = [&](int ks, int buf) {
            uint32_t ab = sb + cons + OM_A + aOff + ks*32;
            uint32_t bb = sb + cons + OM_B + bOff + ks*32;
            ldsm4(afr[buf], ab);
            ldsm2(bfr[buf][0], bb);
            ldsm2(bfr[buf][1], bb + 2176);
        };
        ldf(0, 0);
        #pragma unroll
        for (int s = 0; s < 8; s++) {
            if (s < 7) ldf(s+1, (s+1)&1);
            int bu = s & 1;
            mma16816(acc[0], afr[bu], bfr[bu][0]);
            mma16816(acc[1], afr[bu], bfr[bu][1]);
        }
        __syncthreads();

        if (k2 + OM_DEPTH < K2_) stage(k2 + OM_DEPTH, cons);
        cons += OM_SLOT;
        if (cons == OM_DEPTH*OM_SLOT) cons = 0;
    }

    // epilogue: bias + sigmoid, scatter
    const int r0  = lane >> 2;
    const int cl0 = (lane & 3)*2;
    #pragma unroll
    for (int nt = 0; nt < 2; nt++) {
        #pragma unroll
        for (int j = 0; j < 4; j++) {
            int oc = warp_n*16 + nt*8 + cl0 + (j & 1);
            if (oc >= 27) continue;
            int pcol = warp_m*16 + r0 + (j >> 1)*8;
            int gpix = (b*H_ + row)*W_ + pcol;
            float v = acc[nt][j] + bias_s[oc];
            if (oc >= 18) v = 1.f / (1.f + expf(-v));
            g_offmask[gpix*27 + oc] = v;
        }
    }
}

// ===========================================================================
// Kernel S: sample cols to gmem (fp16, gathers from fp16 x).
// One warp per (pixel, k2) task; lane = 4-channel group.
// ===========================================================================
__global__ void __launch_bounds__(256) sample_cols_kernel() {
    int task = blockIdx.x * 8 + (threadIdx.x >> 5);
    int lane = threadIdx.x & 31;
    int pix = task / 9;
    int k2  = task - pix*9;
    int b   = pix >> 12;
    int rem = pix & 4095;
    int row = rem >> 6;
    int col = rem & 63;

    float offy = g_offmask[pix*27 + 2*k2];
    float offx = g_offmask[pix*27 + 2*k2 + 1];
    float msk  = g_offmask[pix*27 + 18 + k2];
    int ki = k2 / 3, kj = k2 - ki*3;
    float py = (float)(row - 1 + ki) + offy;
    float px = (float)(col - 1 + kj) + offx;
    float y0f = floorf(py), x0f = floorf(px);
    float ly = py - y0f, lx = px - x0f;
    int y0 = (int)y0f, x0 = (int)x0f;
    float w00 = (1.f-ly)*(1.f-lx)*msk;
    float w01 = (1.f-ly)*lx*msk;
    float w10 = ly*(1.f-lx)*msk;
    float w11 = ly*lx*msk;
    bool vy0 = (y0 >= 0) && (y0 < H_);
    bool vy1 = (y0+1 >= 0) && (y0+1 < H_);
    bool vx0 = (x0 >= 0) && (x0 < W_);
    bool vx1 = (x0+1 >= 0) && (x0+1 < W_);
    bool p00 = vy0 && vx0, p01 = vy0 && vx1;
    bool p10 = vy1 && vx0, p11 = vy1 && vx1;
    const uint2* xh2 = (const uint2*)g_xh + (size_t)b * H_ * W_ * 32;
    int i00 = (y0*W_ + x0)*32 + lane;
    uint2 z2 = make_uint2(0, 0);
    uint2 u00 = p00 ? xh2[i00           ] : z2;
    uint2 u01 = p01 ? xh2[i00 + 32      ] : z2;
    uint2 u10 = p10 ? xh2[i00 + W_*32   ] : z2;
    uint2 u11 = p11 ? xh2[i00 + W_*32+32] : z2;
    float2 a00 = __half22float2(*(__half2*)&u00.x);
    float2 b00 = __half22float2(*(__half2*)&u00.y);
    float2 a01 = __half22float2(*(__half2*)&u01.x);
    float2 b01 = __half22float2(*(__half2*)&u01.y);
    float2 a10 = __half22float2(*(__half2*)&u10.x);
    float2 b10 = __half22float2(*(__half2*)&u10.y);
    float2 a11 = __half22float2(*(__half2*)&u11.x);
    float2 b11 = __half22float2(*(__half2*)&u11.y);
    float r0 = w00*a00.x + w01*a01.x + w10*a10.x + w11*a11.x;
    float r1 = w00*a00.y + w01*a01.y + w10*a10.y + w11*a11.y;
    float r2 = w00*b00.x + w01*b01.x + w10*b10.x + w11*b11.x;
    float r3 = w00*b00.y + w01*b01.y + w10*b10.y + w11*b11.y;
    int o = pix*PITCH + k2*64 + lane*2;
    *(uint2*)&g_colh[o] = make_uint2(f16pack(r0, r1), f16pack(r2, r3));
}

// ===========================================================================
// Kernel C: pure GEMM fp16, 3-slot cp.async ring.
// Block = 64 pix (1 row) x 128 oc, 256 threads, 2 blocks/SM. Grid 512.
// Warp tile 32 pix x 32 oc (warp grid 2x4). 18 K-subchunks of 64 channels.
// ===========================================================================
#define G_SLOT 27648
#define G_A 0
#define G_W 9216
#define G_DEPTH 3
#define G_TOTAL (G_DEPTH*G_SLOT)    // 82944

__global__ void __launch_bounds__(256, 2) dcn_gemm_kernel(float* __restrict__ out) {
    extern __shared__ char smem[];
    uint32_t sb = smem_u32(smem);
    const int t    = threadIdx.x;
    const int lane = t & 31;
    const int wid  = t >> 5;        // 0..7
    const int bi   = blockIdx.x;    // 512 blocks, pixels [bi*64, bi*64+64)
    const int b    = bi >> 6;
    const int row  = bi & 63;

    const int warp_m = wid & 1;     // 2 groups of 32 pixels
    const int warp_n = wid >> 1;    // 4 groups of 32 oc
    const uint32_t a_off = (uint32_t)((warp_m*32 + (lane & 15))*144 + (lane >> 4)*16);
    const uint32_t b_off = (uint32_t)((warp_n*32 + (lane & 7))*144 + ((lane >> 3) & 1)*16);

    float acc[2][4][4];
    #pragma unroll
    for (int i = 0; i < 2; i++)
        #pragma unroll
        for (int j = 0; j < 4; j++)
            #pragma unroll
            for (int k = 0; k < 4; k++) acc[i][j][k] = 0.f;

    // A staging: 4 threads per pixel (quarters of the 32-u32 sub-row)
    const int sp = t >> 2;          // pixel 0..63
    const int sq = t & 3;
    const int gA = (bi*64 + sp) * PITCH + sq*8;

    auto stage = [&](int sub, uint32_t slot) {
        uint32_t aso = slot + (uint32_t)(sp*144 + sq*32);
        int gsrc = gA + sub*32;
        #pragma unroll
        for (int j = 0; j < 2; j++)
            CP_A16(sb + G_A + aso + j*16, &g_colh[gsrc + j*4]);
        int k2 = sub >> 1, ch = sub & 1;
        #pragma unroll
        for (int it = 0; it < 4; it++) {
            int idx = it*256 + t;           // 0..1023
            int oc = idx >> 3;
            int g  = idx & 7;
            int gi = k2*8192 + oc*64 + ch*32 + g*4;
            uint32_t so = slot + (uint32_t)(oc*144 + g*16);
            CP_A16(sb + G_W + so, &g_wh[gi]);
        }
        CP_COMMIT();
    };

    stage(0, 0);
    stage(1, G_SLOT);
    stage(2, 2*G_SLOT);
    uint32_t cons = 0;
    for (int sub = 0; sub < 18; sub++) {
        CP_WAIT(2);            // group 'sub' complete
        __syncthreads();

        // ---- software-pipelined MMA: 4 ksteps ----
        uint32_t afr[2][2][4];
        uint32_t bfr[2][4][2];
        auto ldf = [&](int ks, int buf) {
            uint32_t ab = sb + cons + G_A + a_off + ks*32;
            uint32_t bb = sb + cons + G_W + b_off + ks*32;
            ldsm4(afr[buf][0], ab);
            ldsm4(afr[buf][1], ab + 2304);
            ldsm2(bfr[buf][0], bb);
            ldsm2(bfr[buf][1], bb + 1152);
            ldsm2(bfr[buf][2], bb + 2304);
            ldsm2(bfr[buf][3], bb + 3456);
        };
        ldf(0, 0);
        #pragma unroll
        for (int s = 0; s < 4; s++) {
            if (s < 3) ldf(s+1, (s+1)&1);
            int bu = s & 1;
            #pragma unroll
            for (int mt = 0; mt < 2; mt++)
                #pragma unroll
                for (int nt = 0; nt < 4; nt++)
                    mma16816(acc[mt][nt], afr[bu][mt], bfr[bu][nt]);
        }
        __syncthreads();

        if (sub + G_DEPTH < 18) stage(sub + G_DEPTH, cons);
        cons += G_SLOT;
        if (cons == G_DEPTH*G_SLOT) cons = 0;
    }

    // ---- epilogue: transpose through smem, coalesced NCHW stores ----
    float* O_s = (float*)smem;     // [oc][pix 64], stride 68 (34816 B < smem)
    const int g   = lane >> 2;
    const int tig = lane & 3;
    #pragma unroll
    for (int mt = 0; mt < 2; mt++) {
        #pragma unroll
        for (int nt = 0; nt < 4; nt++) {
            int p0 = warp_m*32 + mt*16 + g;
            int o0 = warp_n*32 + nt*8 + tig*2;
            O_s[(o0  )*68 + p0    ] = acc[mt][nt][0];
            O_s[(o0+1)*68 + p0    ] = acc[mt][nt][1];
            O_s[(o0  )*68 + p0 + 8] = acc[mt][nt][2];
            O_s[(o0+1)*68 + p0 + 8] = acc[mt][nt][3];
        }
    }
    __syncthreads();
    // 128 oc x 64 pix = 8192 / 256 = 32 iterations
    #pragma unroll 4
    for (int it = 0; it < 32; it++) {
        int idx = it*256 + t;
        int oc = idx >> 6;
        int p  = idx & 63;
        out[(((size_t)b*O_ + oc)*H_ + row)*W_ + p] = O_s[oc*68 + p];
    }
}

// ===========================================================================
extern "C" void kernel_launch(void* const* d_in, const int* in_sizes, int n_in,
                              void* d_out, int out_size) {
    const float* x      = (const float*)d_in[0];
    const float* weight = (const float*)d_in[1];
    const float* offw   = (const float*)d_in[2];
    const float* offb   = (const float*)d_in[3];
    const float* maskw  = (const float*)d_in[4];
    const float* maskb  = (const float*)d_in[5];
    float* out = (float*)d_out;

    static bool attr_set = false;
    if (!attr_set) {
        cudaFuncSetAttribute(offmask_mma_kernel,
            cudaFuncAttributeMaxDynamicSharedMemorySize, OM_TOTAL);
        cudaFuncSetAttribute(dcn_gemm_kernel,
            cudaFuncAttributeMaxDynamicSharedMemorySize, G_TOTAL);
        attr_set = true;
    }

    transpose_kernel<<<B_*H_*4, 256>>>(x);
    wsplit_kernel<<<(K2_*O_*C_/2 + 255)/256, 256>>>(weight);
    owpack_kernel<<<(K2_*32*C_/2 + 255)/256, 256>>>(offw, maskw);
    offmask_mma_kernel<<<512, 256, OM_TOTAL>>>(offb, maskb);
    sample_cols_kernel<<<NPIX*K2_/8, 256>>>();
    dcn_gemm_kernel<<<512, 256, G_TOTAL>>>(out);
}

// round 17
// speedup vs baseline: 1.0896x; 1.0155x over previous
#include <cuda_runtime.h>
#include <cuda_fp16.h>
#include <math.h>
#include <stdint.h>

// Problem constants
#define B_  8
#define C_  128
#define H_  64
#define W_  64
#define O_  128
#define K2_ 9
#define E_  1152   // C_*K2_
#define NPIX (B_*H_*W_)      // 32768
#define PITCH 576            // u32 per pixel row of cols (1152 fp16 / 2)

// Scratch (device globals; no allocation allowed)
__device__ uint32_t g_xh [B_*H_*W_*C_/2];    // NHWC fp16x2
__device__ float    g_offmask[NPIX*27];      // 18 offsets + 9 sigmoided masks / pixel
__device__ uint32_t g_wh [K2_*O_*C_/2];      // main weight fp16x2, [k2][oc][c/2]
__device__ uint32_t g_owh[K2_*32*C_/2];      // offset/mask weight fp16x2
__device__ uint32_t g_colh[NPIX*PITCH];      // sampled cols fp16x2, [pix][k2][c/2]

// ===========================================================================
// Helpers (baseline PTX: ldmatrix + mma.sync + cp.async)
// ===========================================================================
__device__ __forceinline__ uint32_t smem_u32(const void* p) {
    uint32_t a;
    asm("{ .reg .u64 t; cvta.to.shared.u64 t, %1; cvt.u32.u64 %0, t; }"
        : "=r"(a) : "l"(p));
    return a;
}
__device__ __forceinline__ void ldsm4(uint32_t* r, uint32_t addr) {
    asm volatile("ldmatrix.sync.aligned.m8n8.x4.shared.b16 {%0,%1,%2,%3}, [%4];"
        : "=r"(r[0]), "=r"(r[1]), "=r"(r[2]), "=r"(r[3]) : "r"(addr));
}
__device__ __forceinline__ void ldsm2(uint32_t* r, uint32_t addr) {
    asm volatile("ldmatrix.sync.aligned.m8n8.x2.shared.b16 {%0,%1}, [%2];"
        : "=r"(r[0]), "=r"(r[1]) : "r"(addr));
}
__device__ __forceinline__ void mma16816(float* c, const uint32_t* a, const uint32_t* b) {
    asm volatile(
        "mma.sync.aligned.m16n8k16.row.col.f32.f16.f16.f32 "
        "{%0,%1,%2,%3}, {%4,%5,%6,%7}, {%8,%9}, {%0,%1,%2,%3};"
        : "+f"(c[0]), "+f"(c[1]), "+f"(c[2]), "+f"(c[3])
        : "r"(a[0]), "r"(a[1]), "r"(a[2]), "r"(a[3]), "r"(b[0]), "r"(b[1]));
}
#define CP_A16(dst, src) \
    asm volatile("cp.async.cg.shared.global [%0], [%1], 16;" \
                 :: "r"(dst), "l"(src))
#define CP_A16Z(dst, src, sz) \
    asm volatile("cp.async.cg.shared.global [%0], [%1], 16, %2;" \
                 :: "r"(dst), "l"(src), "r"(sz))
#define CP_COMMIT() asm volatile("cp.async.commit_group;")
#define CP_WAIT(n)  asm volatile("cp.async.wait_group %0;" :: "n"(n))

__device__ __forceinline__ uint32_t f16pack(float a, float b) {
    __half2 h = __floats2half2_rn(a, b);
    return *(uint32_t*)&h;
}

// ===========================================================================
// Kernel A: NCHW -> NHWC transpose -> fp16x2 (smem tile, coalesced)
// ===========================================================================
__global__ void __launch_bounds__(256) transpose_kernel(const float* __restrict__ x) {
    __shared__ float ts[32][65];
    int bi  = blockIdx.x;
    int ct  = bi & 3;
    int rem = bi >> 2;
    int y   = rem & 63;
    int b   = rem >> 6;
    int c0  = ct * 32;
    int t   = threadIdx.x;

    #pragma unroll
    for (int it = 0; it < 8; it++) {
        int idx = it*256 + t;
        int cl = idx >> 6, xw = idx & 63;
        ts[cl][xw] = x[((b*C_ + c0 + cl)*H_ + y)*W_ + xw];
    }
    __syncthreads();
    #pragma unroll
    for (int it = 0; it < 4; it++) {
        int idx = it*256 + t;
        int cp = idx & 15, xw = idx >> 4;
        int o = ((b*H_ + y)*W_ + xw)*64 + (c0 >> 1) + cp;
        g_xh[o] = f16pack(ts[cp*2][xw], ts[cp*2 + 1][xw]);
    }
}

// ===========================================================================
// Kernel A2: main weight fp16 pack into [k2][oc][c] fp16x2
// ===========================================================================
__global__ void wsplit_kernel(const float* __restrict__ w) {
    int i2 = blockIdx.x * blockDim.x + threadIdx.x;
    if (i2 >= K2_*O_*C_/2) return;
    int cpair = i2 & 63;
    int oc    = (i2 >> 6) & 127;
    int k2    = i2 >> 13;
    int c = cpair * 2;
    g_wh[i2] = f16pack(w[oc*E_ + c*K2_ + k2], w[oc*E_ + (c+1)*K2_ + k2]);
}

// ===========================================================================
// Kernel A3: offset/mask weight pack (oc 0..17 offw, 18..26 maskw, rest 0)
// ===========================================================================
__global__ void owpack_kernel(const float* __restrict__ offw,
                              const float* __restrict__ maskw) {
    int i2 = blockIdx.x * blockDim.x + threadIdx.x;
    if (i2 >= K2_*32*C_/2) return;
    int cp  = i2 & 63;
    int oc  = (i2 >> 6) & 31;
    int k2  = i2 >> 11;
    int c = cp * 2;
    float v0 = 0.f, v1 = 0.f;
    if (oc < 18) {
        v0 = offw[oc*E_ + c*K2_ + k2];
        v1 = offw[oc*E_ + (c+1)*K2_ + k2];
    } else if (oc < 27) {
        v0 = maskw[(oc-18)*E_ + c*K2_ + k2];
        v1 = maskw[(oc-18)*E_ + (c+1)*K2_ + k2];
    }
    g_owh[i2] = f16pack(v0, v1);
}

// ===========================================================================
// Kernel B: offset+mask conv via HMMA fp16, 2-slot ring, 4 blocks/SM.
// Block = 64 pix (1 row) x 32 oc, 256 threads. Grid 512.
// NOTE: one group is committed EVERY iteration (empty when nothing to
// stage) so CP_WAIT(DEPTH-1) always pins the group being consumed.
// ===========================================================================
#define OM_SLOT 26112
#define OM_A 0
#define OM_B 17408
#define OM_DEPTH 2
#define OM_BIAS (OM_DEPTH*OM_SLOT)          // 52224
#define OM_TOTAL (OM_DEPTH*OM_SLOT + 128)   // 52352

__global__ void __launch_bounds__(256, 4) offmask_mma_kernel(
    const float* __restrict__ offb, const float* __restrict__ maskb) {
    extern __shared__ char smem[];
    uint32_t sb = smem_u32(smem);
    const int t    = threadIdx.x;
    const int lane = t & 31;
    const int wid  = t >> 5;        // 0..7
    const int bi   = blockIdx.x;    // 512
    const int b    = bi >> 6;
    const int row  = bi & 63;

    float* bias_s = (float*)(smem + OM_BIAS);
    if (t < 32)
        bias_s[t] = (t < 18) ? offb[t] : (t < 27 ? maskb[t-18] : 0.f);

    const int warp_m = wid >> 1;    // 4 groups of 16 pixels
    const int warp_n = wid & 1;     // 2 groups of 16 oc
    const uint32_t aOff = (uint32_t)((warp_m*16 + (lane & 15))*272 + (lane >> 4)*16);
    const uint32_t bOff = (uint32_t)((warp_n*16 + (lane & 7))*272 + ((lane >> 3) & 1)*16);

    float acc[2][4];
    #pragma unroll
    for (int i = 0; i < 2; i++)
        #pragma unroll
        for (int j = 0; j < 4; j++) acc[i][j] = 0.f;

    // A staging: 4 threads per pixel (quarters of the 64-u32 row)
    const int m   = t >> 2;         // pixel (col) 0..63
    const int q   = t & 3;          // quarter
    const int col = m;

    auto stage = [&](int k2, uint32_t slot) {
        // B chunk: 2048 u32 / 256 threads = 2 x 16B each
        #pragma unroll
        for (int it = 0; it < 2; it++) {
            int idx = it*256 + t;
            int oc = idx >> 4;
            int g  = idx & 15;
            int gi = k2*2048 + oc*64 + g*4;
            uint32_t so = slot + (uint32_t)(oc*272 + g*16);
            CP_A16(sb + OM_B + so, &g_owh[gi]);
        }
        // A chunk: im2col with zero-fill
        int ki = k2 / 3, kj = k2 - ki*3;
        int sy = row - 1 + ki;
        int sx = col - 1 + kj;
        bool valid = (sy >= 0) && (sy < H_) && (sx >= 0) && (sx < W_);
        uint32_t sz = valid ? 16u : 0u;
        int syc = valid ? sy : 0;
        int sxc = valid ? sx : 0;
        int gb = ((b*H_ + syc)*W_ + sxc)*64 + q*16;
        uint32_t abase = slot + (uint32_t)(m*272 + q*64);
        #pragma unroll
        for (int j4 = 0; j4 < 4; j4++)
            CP_A16Z(sb + OM_A + abase + j4*16, &g_xh[gb + j4*4], sz);
        CP_COMMIT();
    };

    stage(0, 0);
    stage(1, OM_SLOT);
    uint32_t cons = 0;
    for (int k2 = 0; k2 < K2_; k2++) {
        CP_WAIT(OM_DEPTH-1);   // group k2 complete (uniform 1 group/iter)
        __syncthreads();

        // ---- software-pipelined MMA: 8 ksteps ----
        uint32_t afr[2][4];
        uint32_t bfr[2][2][2];
        auto ldf = [&](int ks, int buf) {
            uint32_t ab = sb + cons + OM_A + aOff + ks*32;
            uint32_t bb = sb + cons + OM_B + bOff + ks*32;
            ldsm4(afr[buf], ab);
            ldsm2(bfr[buf][0], bb);
            ldsm2(bfr[buf][1], bb + 2176);
        };
        ldf(0, 0);
        #pragma unroll
        for (int s = 0; s < 8; s++) {
            if (s < 7) ldf(s+1, (s+1)&1);
            int bu = s & 1;
            mma16816(acc[0], afr[bu], bfr[bu][0]);
            mma16816(acc[1], afr[bu], bfr[bu][1]);
        }
        __syncthreads();

        if (k2 + OM_DEPTH < K2_) stage(k2 + OM_DEPTH, cons);
        else                     CP_COMMIT();     // empty group keeps counting uniform
        cons ^= OM_SLOT;
    }

    // epilogue: bias + sigmoid, scatter
    const int r0  = lane >> 2;
    const int cl0 = (lane & 3)*2;
    #pragma unroll
    for (int nt = 0; nt < 2; nt++) {
        #pragma unroll
        for (int j = 0; j < 4; j++) {
            int oc = warp_n*16 + nt*8 + cl0 + (j & 1);
            if (oc >= 27) continue;
            int pcol = warp_m*16 + r0 + (j >> 1)*8;
            int gpix = (b*H_ + row)*W_ + pcol;
            float v = acc[nt][j] + bias_s[oc];
            if (oc >= 18) v = 1.f / (1.f + expf(-v));
            g_offmask[gpix*27 + oc] = v;
        }
    }
}

// ===========================================================================
// Kernel S: sample cols to gmem (fp16, gathers from fp16 x).
// One warp per (pixel, k2) task; lane = 4-channel group.
// ===========================================================================
__global__ void __launch_bounds__(256) sample_cols_kernel() {
    int task = blockIdx.x * 8 + (threadIdx.x >> 5);
    int lane = threadIdx.x & 31;
    int pix = task / 9;
    int k2  = task - pix*9;
    int b   = pix >> 12;
    int rem = pix & 4095;
    int row = rem >> 6;
    int col = rem & 63;

    float offy = g_offmask[pix*27 + 2*k2];
    float offx = g_offmask[pix*27 + 2*k2 + 1];
    float msk  = g_offmask[pix*27 + 18 + k2];
    int ki = k2 / 3, kj = k2 - ki*3;
    float py = (float)(row - 1 + ki) + offy;
    float px = (float)(col - 1 + kj) + offx;
    float y0f = floorf(py), x0f = floorf(px);
    float ly = py - y0f, lx = px - x0f;
    int y0 = (int)y0f, x0 = (int)x0f;
    float w00 = (1.f-ly)*(1.f-lx)*msk;
    float w01 = (1.f-ly)*lx*msk;
    float w10 = ly*(1.f-lx)*msk;
    float w11 = ly*lx*msk;
    bool vy0 = (y0 >= 0) && (y0 < H_);
    bool vy1 = (y0+1 >= 0) && (y0+1 < H_);
    bool vx0 = (x0 >= 0) && (x0 < W_);
    bool vx1 = (x0+1 >= 0) && (x0+1 < W_);
    bool p00 = vy0 && vx0, p01 = vy0 && vx1;
    bool p10 = vy1 && vx0, p11 = vy1 && vx1;
    const uint2* xh2 = (const uint2*)g_xh + (size_t)b * H_ * W_ * 32;
    int i00 = (y0*W_ + x0)*32 + lane;
    uint2 z2 = make_uint2(0, 0);
    uint2 u00 = p00 ? xh2[i00           ] : z2;
    uint2 u01 = p01 ? xh2[i00 + 32      ] : z2;
    uint2 u10 = p10 ? xh2[i00 + W_*32   ] : z2;
    uint2 u11 = p11 ? xh2[i00 + W_*32+32] : z2;
    float2 a00 = __half22float2(*(__half2*)&u00.x);
    float2 b00 = __half22float2(*(__half2*)&u00.y);
    float2 a01 = __half22float2(*(__half2*)&u01.x);
    float2 b01 = __half22float2(*(__half2*)&u01.y);
    float2 a10 = __half22float2(*(__half2*)&u10.x);
    float2 b10 = __half22float2(*(__half2*)&u10.y);
    float2 a11 = __half22float2(*(__half2*)&u11.x);
    float2 b11 = __half22float2(*(__half2*)&u11.y);
    float r0 = w00*a00.x + w01*a01.x + w10*a10.x + w11*a11.x;
    float r1 = w00*a00.y + w01*a01.y + w10*a10.y + w11*a11.y;
    float r2 = w00*b00.x + w01*b01.x + w10*b10.x + w11*b11.x;
    float r3 = w00*b00.y + w01*b01.y + w10*b10.y + w11*b11.y;
    int o = pix*PITCH + k2*64 + lane*2;
    *(uint2*)&g_colh[o] = make_uint2(f16pack(r0, r1), f16pack(r2, r3));
}

// ===========================================================================
// Kernel C: pure GEMM fp16, 2-slot ring, 3 blocks/SM.
// Block = 64 pix (1 row) x 128 oc, 256 threads. Grid 512.
// Uniform 1-group-per-iteration commit (empty at tail) -> safe CP_WAIT.
// ===========================================================================
#define G_SLOT 27648
#define G_A 0
#define G_W 9216
#define G_DEPTH 2
#define G_TOTAL (G_DEPTH*G_SLOT)    // 55296

__global__ void __launch_bounds__(256, 3) dcn_gemm_kernel(float* __restrict__ out) {
    extern __shared__ char smem[];
    uint32_t sb = smem_u32(smem);
    const int t    = threadIdx.x;
    const int lane = t & 31;
    const int wid  = t >> 5;        // 0..7
    const int bi   = blockIdx.x;    // 512 blocks, pixels [bi*64, bi*64+64)
    const int b    = bi >> 6;
    const int row  = bi & 63;

    const int warp_m = wid & 1;     // 2 groups of 32 pixels
    const int warp_n = wid >> 1;    // 4 groups of 32 oc
    const uint32_t a_off = (uint32_t)((warp_m*32 + (lane & 15))*144 + (lane >> 4)*16);
    const uint32_t b_off = (uint32_t)((warp_n*32 + (lane & 7))*144 + ((lane >> 3) & 1)*16);

    float acc[2][4][4];
    #pragma unroll
    for (int i = 0; i < 2; i++)
        #pragma unroll
        for (int j = 0; j < 4; j++)
            #pragma unroll
            for (int k = 0; k < 4; k++) acc[i][j][k] = 0.f;

    // A staging: 4 threads per pixel (quarters of the 32-u32 sub-row)
    const int sp = t >> 2;          // pixel 0..63
    const int sq = t & 3;
    const int gA = (bi*64 + sp) * PITCH + sq*8;

    auto stage = [&](int sub, uint32_t slot) {
        uint32_t aso = slot + (uint32_t)(sp*144 + sq*32);
        int gsrc = gA + sub*32;
        #pragma unroll
        for (int j = 0; j < 2; j++)
            CP_A16(sb + G_A + aso + j*16, &g_colh[gsrc + j*4]);
        int k2 = sub >> 1, ch = sub & 1;
        #pragma unroll
        for (int it = 0; it < 4; it++) {
            int idx = it*256 + t;           // 0..1023
            int oc = idx >> 3;
            int g  = idx & 7;
            int gi = k2*8192 + oc*64 + ch*32 + g*4;
            uint32_t so = slot + (uint32_t)(oc*144 + g*16);
            CP_A16(sb + G_W + so, &g_wh[gi]);
        }
        CP_COMMIT();
    };

    stage(0, 0);
    stage(1, G_SLOT);
    uint32_t cons = 0;
    for (int sub = 0; sub < 18; sub++) {
        CP_WAIT(G_DEPTH-1);    // group 'sub' complete (uniform 1 group/iter)
        __syncthreads();

        // ---- software-pipelined MMA: 4 ksteps ----
        uint32_t afr[2][2][4];
        uint32_t bfr[2][4][2];
        auto ldf = [&](int ks, int buf) {
            uint32_t ab = sb + cons + G_A + a_off + ks*32;
            uint32_t bb = sb + cons + G_W + b_off + ks*32;
            ldsm4(afr[buf][0], ab);
            ldsm4(afr[buf][1], ab + 2304);
            ldsm2(bfr[buf][0], bb);
            ldsm2(bfr[buf][1], bb + 1152);
            ldsm2(bfr[buf][2], bb + 2304);
            ldsm2(bfr[buf][3], bb + 3456);
        };
        ldf(0, 0);
        #pragma unroll
        for (int s = 0; s < 4; s++) {
            if (s < 3) ldf(s+1, (s+1)&1);
            int bu = s & 1;
            #pragma unroll
            for (int mt = 0; mt < 2; mt++)
                #pragma unroll
                for (int nt = 0; nt < 4; nt++)
                    mma16816(acc[mt][nt], afr[bu][mt], bfr[bu][nt]);
        }
        __syncthreads();

        if (sub + G_DEPTH < 18) stage(sub + G_DEPTH, cons);
        else                    CP_COMMIT();      // empty group keeps counting uniform
        cons ^= G_SLOT;
    }

    // ---- epilogue: transpose through smem, coalesced NCHW stores ----
    float* O_s = (float*)smem;     // [oc][pix 64], stride 68 (34816 B < smem)
    const int g   = lane >> 2;
    const int tig = lane & 3;
    #pragma unroll
    for (int mt = 0; mt < 2; mt++) {
        #pragma unroll
        for (int nt = 0; nt < 4; nt++) {
            int p0 = warp_m*32 + mt*16 + g;
            int o0 = warp_n*32 + nt*8 + tig*2;
            O_s[(o0  )*68 + p0    ] = acc[mt][nt][0];
            O_s[(o0+1)*68 + p0    ] = acc[mt][nt][1];
            O_s[(o0  )*68 + p0 + 8] = acc[mt][nt][2];
            O_s[(o0+1)*68 + p0 + 8] = acc[mt][nt][3];
        }
    }
    __syncthreads();
    // 128 oc x 64 pix = 8192 / 256 = 32 iterations
    #pragma unroll 4
    for (int it = 0; it < 32; it++) {
        int idx = it*256 + t;
        int oc = idx >> 6;
        int p  = idx & 63;
        out[(((size_t)b*O_ + oc)*H_ + row)*W_ + p] = O_s[oc*68 + p];
    }
}

// ===========================================================================
extern "C" void kernel_launch(void* const* d_in, const int* in_sizes, int n_in,
                              void* d_out, int out_size) {
    const float* x      = (const float*)d_in[0];
    const float* weight = (const float*)d_in[1];
    const float* offw   = (const float*)d_in[2];
    const float* offb   = (const float*)d_in[3];
    const float* maskw  = (const float*)d_in[4];
    const float* maskb  = (const float*)d_in[5];
    float* out = (float*)d_out;

    static bool attr_set = false;
    if (!attr_set) {
        cudaFuncSetAttribute(offmask_mma_kernel,
            cudaFuncAttributeMaxDynamicSharedMemorySize, OM_TOTAL);
        cudaFuncSetAttribute(dcn_gemm_kernel,
            cudaFuncAttributeMaxDynamicSharedMemorySize, G_TOTAL);
        attr_set = true;
    }

    transpose_kernel<<<B_*H_*4, 256>>>(x);
    wsplit_kernel<<<(K2_*O_*C_/2 + 255)/256, 256>>>(weight);
    owpack_kernel<<<(K2_*32*C_/2 + 255)/256, 256>>>(offw, maskw);
    offmask_mma_kernel<<<512, 256, OM_TOTAL>>>(offb, maskb);
    sample_cols_kernel<<<NPIX*K2_/8, 256>>>();
    dcn_gemm_kernel<<<512, 256, G_TOTAL>>>(out);
}